// round 2
// baseline (speedup 1.0000x reference)
#include <cuda_runtime.h>

// Problem constants: B=4, S=512, D=768, L=64
#define B_ 4
#define S_ 512
#define D_ 768
#define L_ 64

// Scratch for rank-1 terms: t2h[b,l,i], t2d[b,l,o]  (B*L*S floats each = 512 KB)
__device__ float g_t2h[B_ * L_ * S_];
__device__ float g_t2d[B_ * L_ * S_];

// ---------------------------------------------------------------------------
// Packed f32x2 helpers (Blackwell FFMA2 path — 2x fp32 FMA throughput)
// ---------------------------------------------------------------------------
__device__ __forceinline__ unsigned long long bcast2(float v) {
    unsigned long long p;
    asm("mov.b64 %0, {%1, %1};" : "=l"(p) : "f"(v));
    return p;
}
__device__ __forceinline__ void fma2(unsigned long long& c, unsigned long long a,
                                     unsigned long long b) {
    asm("fma.rn.f32x2 %0, %1, %2, %0;" : "+l"(c) : "l"(a), "l"(b));
}
__device__ __forceinline__ float2 unpack2(unsigned long long p) {
    float2 r;
    asm("mov.b64 {%0, %1}, %2;" : "=f"(r.x), "=f"(r.y) : "l"(p));
    return r;
}

// ---------------------------------------------------------------------------
// Kernel 1: t2h[b,l,i] = head[b,i,:] . W[l,0:D],  t2d[b,l,o] = dep[b,o,:] . W[l,D:2D]
// One block per (b,l); warp-per-row with lane-parallel dot + shuffle reduce.
// ---------------------------------------------------------------------------
__global__ void t2_kernel(const float* __restrict__ head,
                          const float* __restrict__ dep,
                          const float* __restrict__ W) {
    int bl = blockIdx.x;
    int b = bl / L_, l = bl % L_;
    int warp = threadIdx.x >> 5, lane = threadIdx.x & 31;
    const float* Wh = W + (size_t)l * (2 * D_);
    const float* Wd = Wh + D_;
    for (int i = warp; i < S_; i += 8) {
        const float* hr = head + ((size_t)b * S_ + i) * D_;
        const float* dr = dep  + ((size_t)b * S_ + i) * D_;
        float sh = 0.f, sd = 0.f;
        #pragma unroll 4
        for (int d = lane; d < D_; d += 32) {
            sh += hr[d] * Wh[d];
            sd += dr[d] * Wd[d];
        }
        #pragma unroll
        for (int off = 16; off; off >>= 1) {
            sh += __shfl_down_sync(0xffffffffu, sh, off);
            sd += __shfl_down_sync(0xffffffffu, sd, off);
        }
        if (lane == 0) {
            g_t2h[(size_t)bl * S_ + i] = sh;
            g_t2d[(size_t)bl * S_ + i] = sd;
        }
    }
}

// ---------------------------------------------------------------------------
// Kernel 2: per (b,l): out[i,o] = sum_d (head[b,i,d]*U[l,d]) * dep[b,o,d]
//                               + t2h[b,l,i] + t2d[b,l,o] + bias[l]
// 128x128 block tile, BK=16, 256 threads, 8x8 micro-tile, FFMA2 accumulation.
// ---------------------------------------------------------------------------
#define BM 128
#define BN 128
#define BK 16
#define LDA 132   // 128 + 4 pad (limits transposed-store conflicts to 2-way)

__global__ __launch_bounds__(256, 2)
void biaffine_kernel(const float* __restrict__ head,
                     const float* __restrict__ dep,
                     const float* __restrict__ U,
                     const float* __restrict__ bias,
                     float* __restrict__ out) {
    __shared__ __align__(16) float As[BK][LDA];   // scaled head, [k][i]
    __shared__ __align__(16) float Bs[BK][LDA];   // dep, [k][o]
    __shared__ float Us[D_];

    const int bl = blockIdx.z;
    const int b = bl >> 6;        // / L_
    const int l = bl & (L_ - 1);
    const int i0 = blockIdx.y * BM;
    const int o0 = blockIdx.x * BN;
    const int tid = threadIdx.x;
    const int tx = tid & 15;      // -> o micro (8 cols)
    const int ty = tid >> 4;      // -> i micro (8 rows)

    // Stage U[l,:] once
    for (int d = tid; d < D_; d += 256) Us[d] = U[(size_t)l * D_ + d];

    // acc[n][mp] packs rows (2*mp, 2*mp+1) of column n
    unsigned long long acc[8][4];
    #pragma unroll
    for (int n = 0; n < 8; n++)
        #pragma unroll
        for (int mp = 0; mp < 4; mp++) acc[n][mp] = 0ull;

    const float* hbase = head + ((size_t)b * S_ + i0) * D_;
    const float* dbase = dep  + ((size_t)b * S_ + o0) * D_;

    const int lr = tid >> 2;          // 0..63
    const int lc = (tid & 3) * 4;     // 0,4,8,12

    for (int kt = 0; kt < D_ / BK; kt++) {
        const int d0 = kt * BK;
        __syncthreads();   // (also covers Us staging on first iteration)
        #pragma unroll
        for (int j = 0; j < 2; j++) {
            int r = j * 64 + lr;
            float4 hv = *(const float4*)(hbase + (size_t)r * D_ + d0 + lc);
            As[lc + 0][r] = hv.x * Us[d0 + lc + 0];
            As[lc + 1][r] = hv.y * Us[d0 + lc + 1];
            As[lc + 2][r] = hv.z * Us[d0 + lc + 2];
            As[lc + 3][r] = hv.w * Us[d0 + lc + 3];
            float4 dv = *(const float4*)(dbase + (size_t)r * D_ + d0 + lc);
            Bs[lc + 0][r] = dv.x;
            Bs[lc + 1][r] = dv.y;
            Bs[lc + 2][r] = dv.z;
            Bs[lc + 3][r] = dv.w;
        }
        __syncthreads();

        #pragma unroll
        for (int k = 0; k < BK; k++) {
            const float* arow = &As[k][ty * 8];
            ulonglong2 a01 = *(const ulonglong2*)(arow);
            ulonglong2 a23 = *(const ulonglong2*)(arow + 4);
            unsigned long long ap[4] = {a01.x, a01.y, a23.x, a23.y};
            const float* brow = &Bs[k][tx * 8];
            float4 b0 = *(const float4*)(brow);
            float4 b1 = *(const float4*)(brow + 4);
            float bv[8] = {b0.x, b0.y, b0.z, b0.w, b1.x, b1.y, b1.z, b1.w};
            #pragma unroll
            for (int n = 0; n < 8; n++) {
                unsigned long long bb = bcast2(bv[n]);
                #pragma unroll
                for (int mp = 0; mp < 4; mp++) fma2(acc[n][mp], ap[mp], bb);
            }
        }
    }

    // Unpack accumulators
    float r[8][8];
    #pragma unroll
    for (int n = 0; n < 8; n++)
        #pragma unroll
        for (int mp = 0; mp < 4; mp++) {
            float2 p = unpack2(acc[n][mp]);
            r[2 * mp + 0][n] = p.x;
            r[2 * mp + 1][n] = p.y;
        }

    // Epilogue: + t2h[i] + t2d[o] + bias[l]
    const float bz = bias[l];
    const float* t2h = g_t2h + (size_t)bl * S_;
    const float* t2d = g_t2d + (size_t)bl * S_;
    float td[8];
    #pragma unroll
    for (int n = 0; n < 8; n++) td[n] = t2d[o0 + tx * 8 + n];

    float* obase = out + (size_t)bl * S_ * S_;
    #pragma unroll
    for (int m = 0; m < 8; m++) {
        int i = i0 + ty * 8 + m;
        float ai = t2h[i] + bz;
        float4 v0 = make_float4(r[m][0] + td[0] + ai, r[m][1] + td[1] + ai,
                                r[m][2] + td[2] + ai, r[m][3] + td[3] + ai);
        float4 v1 = make_float4(r[m][4] + td[4] + ai, r[m][5] + td[5] + ai,
                                r[m][6] + td[6] + ai, r[m][7] + td[7] + ai);
        float* orow = obase + (size_t)i * S_ + o0 + tx * 8;
        *(float4*)(orow)     = v0;
        *(float4*)(orow + 4) = v1;
    }
}

// ---------------------------------------------------------------------------
extern "C" void kernel_launch(void* const* d_in, const int* in_sizes, int n_in,
                              void* d_out, int out_size) {
    const float* head = (const float*)d_in[0];  // (B,S,D)
    const float* dep  = (const float*)d_in[1];  // (B,S,D)
    const float* U    = (const float*)d_in[2];  // (L,D)
    const float* W    = (const float*)d_in[3];  // (L,2D)
    const float* bias = (const float*)d_in[4];  // (L,)
    float* out = (float*)d_out;                 // (B,L,S,S)

    t2_kernel<<<B_ * L_, 256>>>(head, dep, W);

    dim3 grid(S_ / BN, S_ / BM, B_ * L_);
    biaffine_kernel<<<grid, 256>>>(head, dep, U, bias, out);
}

// round 4
// speedup vs baseline: 1.8174x; 1.8174x over previous
#include <cuda_runtime.h>
#include <cuda_bf16.h>
#include <cstdint>

#define B_ 4
#define S_ 512
#define D_ 768
#define L_ 64

// ---------------------------------------------------------------------------
// Global scratch
// ---------------------------------------------------------------------------
__device__ float g_t2h[B_ * L_ * S_];
__device__ float g_t2d[B_ * L_ * S_];
__device__ __nv_bfloat16 g_dep_hi[B_ * S_ * D_];
__device__ __nv_bfloat16 g_dep_lo[B_ * S_ * D_];

// ---------------------------------------------------------------------------
// PTX helpers (all baseline sm_80-class — legal at compute_103)
// ---------------------------------------------------------------------------
__device__ __forceinline__ uint32_t smem_to_u32(const void* p) {
    uint32_t a;
    asm("{ .reg .u64 t; cvta.to.shared.u64 t, %1; cvt.u32.u64 %0, t; }" : "=r"(a) : "l"(p));
    return a;
}
__device__ __forceinline__ void cp16(uint32_t dst, const void* src) {
    asm volatile("cp.async.cg.shared.global [%0], [%1], 16;" :: "r"(dst), "l"(src));
}
__device__ __forceinline__ void cp_commit() {
    asm volatile("cp.async.commit_group;" ::: "memory");
}
template <int N> __device__ __forceinline__ void cp_wait() {
    asm volatile("cp.async.wait_group %0;" :: "n"(N) : "memory");
}
__device__ __forceinline__ void ldsm4(uint32_t r[4], uint32_t addr) {
    asm volatile("ldmatrix.sync.aligned.m8n8.x4.shared.b16 {%0,%1,%2,%3}, [%4];"
                 : "=r"(r[0]), "=r"(r[1]), "=r"(r[2]), "=r"(r[3]) : "r"(addr));
}
__device__ __forceinline__ void mma16816(float c[4], const uint32_t a[4], const uint32_t b[2]) {
    asm volatile("mma.sync.aligned.m16n8k16.row.col.f32.bf16.bf16.f32 "
                 "{%0,%1,%2,%3}, {%4,%5,%6,%7}, {%8,%9}, {%0,%1,%2,%3};"
                 : "+f"(c[0]), "+f"(c[1]), "+f"(c[2]), "+f"(c[3])
                 : "r"(a[0]), "r"(a[1]), "r"(a[2]), "r"(a[3]), "r"(b[0]), "r"(b[1]));
}
__device__ __forceinline__ uint32_t pack_bf16(__nv_bfloat16 a, __nv_bfloat16 b) {
    return (uint32_t)__bfloat16_as_ushort(a) | ((uint32_t)__bfloat16_as_ushort(b) << 16);
}

// ---------------------------------------------------------------------------
// Prep kernel: split dep into bf16 hi/lo
// ---------------------------------------------------------------------------
__global__ void split_dep_kernel(const float* __restrict__ dep) {
    int idx = blockIdx.x * blockDim.x + threadIdx.x;  // one float4 per thread
    float4 v = ((const float4*)dep)[idx];
    float f[4] = {v.x, v.y, v.z, v.w};
    __nv_bfloat16 h[4], l[4];
#pragma unroll
    for (int q = 0; q < 4; q++) {
        h[q] = __float2bfloat16(f[q]);
        l[q] = __float2bfloat16(f[q] - __bfloat162float(h[q]));
    }
    ((uint2*)g_dep_hi)[idx] = make_uint2(pack_bf16(h[0], h[1]), pack_bf16(h[2], h[3]));
    ((uint2*)g_dep_lo)[idx] = make_uint2(pack_bf16(l[0], l[1]), pack_bf16(l[2], l[3]));
}

// ---------------------------------------------------------------------------
// Prep kernel: rank-1 terms
// ---------------------------------------------------------------------------
__global__ void t2_kernel(const float* __restrict__ head,
                          const float* __restrict__ dep,
                          const float* __restrict__ W) {
    int bl = blockIdx.x;
    int b = bl / L_, l = bl % L_;
    int warp = threadIdx.x >> 5, lane = threadIdx.x & 31;
    const float* Wh = W + (size_t)l * (2 * D_);
    const float* Wd = Wh + D_;
    for (int i = warp; i < S_; i += 8) {
        const float* hr = head + ((size_t)b * S_ + i) * D_;
        const float* dr = dep + ((size_t)b * S_ + i) * D_;
        float sh = 0.f, sd = 0.f;
#pragma unroll 4
        for (int d = lane; d < D_; d += 32) {
            sh += hr[d] * Wh[d];
            sd += dr[d] * Wd[d];
        }
#pragma unroll
        for (int off = 16; off; off >>= 1) {
            sh += __shfl_down_sync(0xffffffffu, sh, off);
            sd += __shfl_down_sync(0xffffffffu, sd, off);
        }
        if (lane == 0) {
            g_t2h[(size_t)bl * S_ + i] = sh;
            g_t2d[(size_t)bl * S_ + i] = sd;
        }
    }
}

// ---------------------------------------------------------------------------
// Main GEMM: per (b,l,i-tile,o-tile) 128x128 tile.
// C = Ah·Bh^T + Ah·Bl^T + Al·Bh^T  (bf16x3), A = head ⊙ U[l] split on the fly.
// 8 warps: 2 (m) x 4 (n), warp tile 64x32, m16n8k16 HMMA, fp32 accum.
// Dynamic smem:
//   [0,3072)        Us (U[l,:])
//   [3072,44032)    A tiles: [stage][hi/lo] 128 x LDT(40) bf16 (10240 B each)
//   [44032,84992)   B tiles: same layout
// ---------------------------------------------------------------------------
#define BK 32
#define NKT (D_ / BK) /* 24 */
#define LDT 40        /* padded row stride in bf16 elems (80 B) */
#define TILE_B 10240  /* 128*LDT*2 */
#define OFF_A 3072
#define OFF_B 44032
#define ABUF(s, hl) (OFF_A + ((s) * 2 + (hl)) * TILE_B)
#define BBUF(s, hl) (OFF_B + ((s) * 2 + (hl)) * TILE_B)
#define SMEM_TOTAL 84992

__global__ __launch_bounds__(256, 1)
void biaffine_mma_kernel(const float* __restrict__ head,
                         const float* __restrict__ U,
                         const float* __restrict__ bias,
                         float* __restrict__ out) {
    extern __shared__ __align__(16) char smem[];
    const uint32_t sb = smem_to_u32(smem);
    float* Us = (float*)smem;

    const int tid = threadIdx.x;
    const int wid = tid >> 5, lane = tid & 31;
    const int wm = wid & 1, wn = wid >> 1;
    const int bl = blockIdx.z;
    const int b = bl >> 6, l = bl & (L_ - 1);
    const int i0 = blockIdx.y * 128;
    const int o0 = blockIdx.x * 128;

    for (int d = tid; d < D_; d += 256) Us[d] = U[(size_t)l * D_ + d];
    __syncthreads();

    const float* hbase = head + ((size_t)b * S_ + i0) * D_;
    const __nv_bfloat16* dhb = g_dep_hi + ((size_t)b * S_ + o0) * D_;
    const __nv_bfloat16* dlb = g_dep_lo + ((size_t)b * S_ + o0) * D_;

    float4 areg[4];

    // ---- helpers as macros over locals ----
#define LOAD_A(kt)                                                                 \
    do {                                                                           \
        const int d0 = (kt) * BK;                                                  \
        _Pragma("unroll") for (int j = 0; j < 4; j++) {                            \
            int f4 = j * 256 + tid;                                                \
            int row = f4 >> 3, c4 = (f4 & 7) * 4;                                  \
            float4 v = *(const float4*)(hbase + (size_t)row * D_ + d0 + c4);       \
            v.x *= Us[d0 + c4];                                                    \
            v.y *= Us[d0 + c4 + 1];                                                \
            v.z *= Us[d0 + c4 + 2];                                                \
            v.w *= Us[d0 + c4 + 3];                                                \
            areg[j] = v;                                                           \
        }                                                                          \
    } while (0)

#define STORE_A(s)                                                                 \
    do {                                                                           \
        _Pragma("unroll") for (int j = 0; j < 4; j++) {                            \
            int f4 = j * 256 + tid;                                                \
            int row = f4 >> 3, c4 = (f4 & 7) * 4;                                  \
            float f[4] = {areg[j].x, areg[j].y, areg[j].z, areg[j].w};             \
            __nv_bfloat16 h[4], lo[4];                                             \
            _Pragma("unroll") for (int q = 0; q < 4; q++) {                        \
                h[q] = __float2bfloat16(f[q]);                                     \
                lo[q] = __float2bfloat16(f[q] - __bfloat162float(h[q]));           \
            }                                                                      \
            uint32_t byo = (uint32_t)(row * LDT + c4) * 2;                         \
            *(uint2*)(smem + ABUF(s, 0) + byo) =                                   \
                make_uint2(pack_bf16(h[0], h[1]), pack_bf16(h[2], h[3]));          \
            *(uint2*)(smem + ABUF(s, 1) + byo) =                                   \
                make_uint2(pack_bf16(lo[0], lo[1]), pack_bf16(lo[2], lo[3]));      \
        }                                                                          \
    } while (0)

#define CP_B(s, kt)                                                                \
    do {                                                                           \
        const int d0 = (kt) * BK;                                                  \
        _Pragma("unroll") for (int j = 0; j < 2; j++) {                            \
            int ch = j * 256 + tid;                                                \
            int row = ch >> 2, c16 = (ch & 3) * 8;                                 \
            uint32_t byo = (uint32_t)(row * LDT + c16) * 2;                        \
            cp16(sb + BBUF(s, 0) + byo, dhb + (size_t)row * D_ + d0 + c16);        \
            cp16(sb + BBUF(s, 1) + byo, dlb + (size_t)row * D_ + d0 + c16);        \
        }                                                                          \
    } while (0)

    float cacc[4][4][4];
#pragma unroll
    for (int mt = 0; mt < 4; mt++)
#pragma unroll
        for (int nt = 0; nt < 4; nt++)
#pragma unroll
            for (int q = 0; q < 4; q++) cacc[mt][nt][q] = 0.f;

    // ldmatrix lane-address offsets (bytes within a tile)
    const uint32_t a_lm = (uint32_t)(((wm * 64 + (lane & 15)) * LDT + (lane >> 4) * 8) * 2);
    const uint32_t b_lm = (uint32_t)(((wn * 32 + (lane & 7) + ((lane >> 4) << 3)) * LDT +
                                      (((lane >> 3) & 1) * 8)) * 2);

    // ---- prologue ----
    LOAD_A(0);
    CP_B(0, 0);
    cp_commit();
    STORE_A(0);
    LOAD_A(1);
    CP_B(1, 1);
    cp_commit();
    cp_wait<1>();
    __syncthreads();

    // ---- main loop ----
    for (int kt = 0; kt < NKT; kt++) {
        const int cur = kt & 1, nxt = cur ^ 1;
        const uint32_t baseAh = sb + ABUF(cur, 0) + a_lm;
        const uint32_t baseAl = sb + ABUF(cur, 1) + a_lm;
        const uint32_t baseBh = sb + BBUF(cur, 0) + b_lm;
        const uint32_t baseBl = sb + BBUF(cur, 1) + b_lm;
#pragma unroll
        for (int ks = 0; ks < 2; ks++) {
            const uint32_t ko = ks * 32;  // 16 elems * 2B
            uint32_t ah[4][4], al[4][4], bh[4][2], bo[4][2];
#pragma unroll
            for (int mt = 0; mt < 4; mt++) ldsm4(ah[mt], baseAh + mt * (16 * LDT * 2) + ko);
#pragma unroll
            for (int mt = 0; mt < 4; mt++) ldsm4(al[mt], baseAl + mt * (16 * LDT * 2) + ko);
#pragma unroll
            for (int nt2 = 0; nt2 < 2; nt2++) {
                uint32_t t[4];
                ldsm4(t, baseBh + nt2 * (16 * LDT * 2) + ko);
                bh[nt2 * 2][0] = t[0]; bh[nt2 * 2][1] = t[1];
                bh[nt2 * 2 + 1][0] = t[2]; bh[nt2 * 2 + 1][1] = t[3];
                ldsm4(t, baseBl + nt2 * (16 * LDT * 2) + ko);
                bo[nt2 * 2][0] = t[0]; bo[nt2 * 2][1] = t[1];
                bo[nt2 * 2 + 1][0] = t[2]; bo[nt2 * 2 + 1][1] = t[3];
            }
#pragma unroll
            for (int mt = 0; mt < 4; mt++)
#pragma unroll
                for (int nt = 0; nt < 4; nt++) {
                    mma16816(cacc[mt][nt], ah[mt], bh[nt]);
                    mma16816(cacc[mt][nt], ah[mt], bo[nt]);
                    mma16816(cacc[mt][nt], al[mt], bh[nt]);
                }
        }
        if (kt < NKT - 1) {
            STORE_A(nxt);  // areg holds A(kt+1); sA[nxt] last read 2 iters ago (synced)
            __syncthreads();
            if (kt + 2 < NKT) {
                LOAD_A(kt + 2);
                CP_B(cur, kt + 2);
                cp_commit();
                cp_wait<1>();
            } else {
                cp_wait<0>();
            }
            __syncthreads();
        }
    }

    // ---- epilogue: + t2h[i] + t2d[o] + bias[l] ----
    const float* t2h = g_t2h + (size_t)bl * S_;
    const float* t2d = g_t2d + (size_t)bl * S_;
    const float bz = bias[l];
    float* obase = out + (size_t)bl * S_ * S_;
#pragma unroll
    for (int mt = 0; mt < 4; mt++) {
        const int i_lo = i0 + wm * 64 + mt * 16 + (lane >> 2);
        const float ai0 = t2h[i_lo] + bz;
        const float ai1 = t2h[i_lo + 8] + bz;
        float* row0 = obase + (size_t)i_lo * S_;
        float* row1 = row0 + 8 * S_;
#pragma unroll
        for (int nt = 0; nt < 4; nt++) {
            const int o_ = o0 + wn * 32 + nt * 8 + (lane & 3) * 2;
            const float td0 = t2d[o_], td1 = t2d[o_ + 1];
            *(float2*)(row0 + o_) =
                make_float2(cacc[mt][nt][0] + td0 + ai0, cacc[mt][nt][1] + td1 + ai0);
            *(float2*)(row1 + o_) =
                make_float2(cacc[mt][nt][2] + td0 + ai1, cacc[mt][nt][3] + td1 + ai1);
        }
    }
#undef LOAD_A
#undef STORE_A
#undef CP_B
}

// ---------------------------------------------------------------------------
extern "C" void kernel_launch(void* const* d_in, const int* in_sizes, int n_in,
                              void* d_out, int out_size) {
    const float* head = (const float*)d_in[0];  // (B,S,D)
    const float* dep  = (const float*)d_in[1];  // (B,S,D)
    const float* U    = (const float*)d_in[2];  // (L,D)
    const float* W    = (const float*)d_in[3];  // (L,2D)
    const float* bias = (const float*)d_in[4];  // (L,)
    float* out = (float*)d_out;                 // (B,L,S,S)

    static bool attr_set = false;
    if (!attr_set) {
        cudaFuncSetAttribute(biaffine_mma_kernel,
                             cudaFuncAttributeMaxDynamicSharedMemorySize, SMEM_TOTAL);
        attr_set = true;
    }

    split_dep_kernel<<<(B_ * S_ * D_ / 4) / 256, 256>>>(dep);
    t2_kernel<<<B_ * L_, 256>>>(head, dep, W);

    dim3 grid(4, 4, B_ * L_);  // o-tile fastest -> consecutive CTAs share B tile in L2
    biaffine_mma_kernel<<<grid, 256, SMEM_TOTAL>>>(head, U, bias, out);
}

// round 6
// speedup vs baseline: 1.9414x; 1.0682x over previous
#include <cuda_runtime.h>
#include <cuda_bf16.h>
#include <cstdint>

#define B_ 4
#define S_ 512
#define D_ 768
#define L_ 64

// ---------------------------------------------------------------------------
// Global scratch (static __device__ arrays — allocation-free at launch time)
// ---------------------------------------------------------------------------
__device__ float g_t2h[B_ * L_ * S_];
__device__ float g_t2d[B_ * L_ * S_];
__device__ __nv_bfloat16 g_dep_hi[B_ * S_ * D_];   //  6 MB
__device__ __nv_bfloat16 g_dep_lo[B_ * S_ * D_];   //  6 MB
__device__ __nv_bfloat16 g_a_hi[(size_t)B_ * L_ * S_ * D_];  // 201 MB
__device__ __nv_bfloat16 g_a_lo[(size_t)B_ * L_ * S_ * D_];  // 201 MB

// ---------------------------------------------------------------------------
// PTX helpers (baseline sm_80-class — legal at compute_103)
// ---------------------------------------------------------------------------
__device__ __forceinline__ uint32_t smem_to_u32(const void* p) {
    uint32_t a;
    asm("{ .reg .u64 t; cvta.to.shared.u64 t, %1; cvt.u32.u64 %0, t; }" : "=r"(a) : "l"(p));
    return a;
}
__device__ __forceinline__ void cp16(uint32_t dst, const void* src) {
    asm volatile("cp.async.cg.shared.global [%0], [%1], 16;" :: "r"(dst), "l"(src));
}
__device__ __forceinline__ void cp_commit() {
    asm volatile("cp.async.commit_group;" ::: "memory");
}
template <int N> __device__ __forceinline__ void cp_wait() {
    asm volatile("cp.async.wait_group %0;" :: "n"(N) : "memory");
}
__device__ __forceinline__ void ldsm4(uint32_t r[4], uint32_t addr) {
    asm volatile("ldmatrix.sync.aligned.m8n8.x4.shared.b16 {%0,%1,%2,%3}, [%4];"
                 : "=r"(r[0]), "=r"(r[1]), "=r"(r[2]), "=r"(r[3]) : "r"(addr));
}
__device__ __forceinline__ void mma16816(float c[4], const uint32_t a[4], const uint32_t b[2]) {
    asm volatile("mma.sync.aligned.m16n8k16.row.col.f32.bf16.bf16.f32 "
                 "{%0,%1,%2,%3}, {%4,%5,%6,%7}, {%8,%9}, {%0,%1,%2,%3};"
                 : "+f"(c[0]), "+f"(c[1]), "+f"(c[2]), "+f"(c[3])
                 : "r"(a[0]), "r"(a[1]), "r"(a[2]), "r"(a[3]), "r"(b[0]), "r"(b[1]));
}
__device__ __forceinline__ uint32_t pack_bf16(__nv_bfloat16 a, __nv_bfloat16 b) {
    return (uint32_t)__bfloat16_as_ushort(a) | ((uint32_t)__bfloat16_as_ushort(b) << 16);
}

// ---------------------------------------------------------------------------
// Prep 1: split dep into bf16 hi/lo
// ---------------------------------------------------------------------------
__global__ void split_dep_kernel(const float* __restrict__ dep) {
    int idx = blockIdx.x * blockDim.x + threadIdx.x;  // one float4 per thread
    float4 v = ((const float4*)dep)[idx];
    float f[4] = {v.x, v.y, v.z, v.w};
    __nv_bfloat16 h[4], l[4];
#pragma unroll
    for (int q = 0; q < 4; q++) {
        h[q] = __float2bfloat16(f[q]);
        l[q] = __float2bfloat16(f[q] - __bfloat162float(h[q]));
    }
    ((uint2*)g_dep_hi)[idx] = make_uint2(pack_bf16(h[0], h[1]), pack_bf16(h[2], h[3]));
    ((uint2*)g_dep_lo)[idx] = make_uint2(pack_bf16(l[0], l[1]), pack_bf16(l[2], l[3]));
}

// ---------------------------------------------------------------------------
// Prep 2: A[bl,i,d] = head[b,i,d] * U[l,d], split to bf16 hi/lo
// grid: ( S*D/4/256 = 384, B*L = 256 )
// ---------------------------------------------------------------------------
__global__ void prep_a_kernel(const float* __restrict__ head,
                              const float* __restrict__ U) {
    const int bl = blockIdx.y;
    const int b = bl >> 6, l = bl & (L_ - 1);
    const int idx2 = blockIdx.x * 256 + threadIdx.x;  // 0..S*D/4-1
    const int d4 = idx2 % (D_ / 4);
    const int i = idx2 / (D_ / 4);
    float4 h = ((const float4*)head)[(size_t)(b * S_ + i) * (D_ / 4) + d4];
    float4 u = ((const float4*)U)[(size_t)l * (D_ / 4) + d4];
    float f[4] = {h.x * u.x, h.y * u.y, h.z * u.z, h.w * u.w};
    __nv_bfloat16 hi[4], lo[4];
#pragma unroll
    for (int q = 0; q < 4; q++) {
        hi[q] = __float2bfloat16(f[q]);
        lo[q] = __float2bfloat16(f[q] - __bfloat162float(hi[q]));
    }
    size_t o = (size_t)bl * (S_ * (D_ / 4)) + idx2;
    ((uint2*)g_a_hi)[o] = make_uint2(pack_bf16(hi[0], hi[1]), pack_bf16(hi[2], hi[3]));
    ((uint2*)g_a_lo)[o] = make_uint2(pack_bf16(lo[0], lo[1]), pack_bf16(lo[2], lo[3]));
}

// ---------------------------------------------------------------------------
// Prep 3: rank-1 terms
// ---------------------------------------------------------------------------
__global__ void t2_kernel(const float* __restrict__ head,
                          const float* __restrict__ dep,
                          const float* __restrict__ W) {
    int bl = blockIdx.x;
    int b = bl / L_, l = bl % L_;
    int warp = threadIdx.x >> 5, lane = threadIdx.x & 31;
    const float* Wh = W + (size_t)l * (2 * D_);
    const float* Wd = Wh + D_;
    for (int i = warp; i < S_; i += 8) {
        const float* hr = head + ((size_t)b * S_ + i) * D_;
        const float* dr = dep + ((size_t)b * S_ + i) * D_;
        float sh = 0.f, sd = 0.f;
#pragma unroll 4
        for (int d = lane; d < D_; d += 32) {
            sh += hr[d] * Wh[d];
            sd += dr[d] * Wd[d];
        }
#pragma unroll
        for (int off = 16; off; off >>= 1) {
            sh += __shfl_down_sync(0xffffffffu, sh, off);
            sd += __shfl_down_sync(0xffffffffu, sd, off);
        }
        if (lane == 0) {
            g_t2h[(size_t)bl * S_ + i] = sh;
            g_t2d[(size_t)bl * S_ + i] = sd;
        }
    }
}

// ---------------------------------------------------------------------------
// Main GEMM: C = Ah·Bh^T + Ah·Bl^T + Al·Bh^T  (bf16x3, fp32 accum)
// All four operand tiles precomputed bf16 in global, loaded via cp.async.
// 128x128 CTA tile, BK=32, 8 warps (2m x 4n, warp tile 64x32), 2 stages,
// 2 CTAs/SM. Dynamic smem: 2 stages x 4 tiles x 10240 B = 81920 B.
//   tile order within stage: Ah, Al, Bh, Bl; row stride LDT=40 bf16 (80 B).
// ---------------------------------------------------------------------------
#define BK 32
#define NKT (D_ / BK) /* 24 */
#define LDT 40
#define TILE_B 10240
#define STAGE_B 40960
#define SMEM_TOTAL 81920

__global__ __launch_bounds__(256, 2)
void biaffine_mma_kernel(const float* __restrict__ bias,
                         float* __restrict__ out) {
    extern __shared__ __align__(16) char smem[];
    const uint32_t sb = smem_to_u32(smem);

    const int tid = threadIdx.x;
    const int wid = tid >> 5, lane = tid & 31;
    const int wm = wid & 1, wn = wid >> 1;
    const int bl = blockIdx.z;
    const int b = bl >> 6, l = bl & (L_ - 1);
    const int i0 = (blockIdx.x >> 2) * 128;
    const int o0 = (blockIdx.x & 3) * 128;

    const char* ah_g = (const char*)(g_a_hi + ((size_t)bl * S_ + i0) * D_);
    const char* al_g = (const char*)(g_a_lo + ((size_t)bl * S_ + i0) * D_);
    const char* bh_g = (const char*)(g_dep_hi + ((size_t)b * S_ + o0) * D_);
    const char* bl_g = (const char*)(g_dep_lo + ((size_t)b * S_ + o0) * D_);

#define CP_STAGE(s, kt)                                                           \
    do {                                                                          \
        const int d0b = (kt) * (BK * 2);                                          \
        _Pragma("unroll") for (int j = 0; j < 8; j++) {                           \
            const int c = ((j & 1) << 8) | tid;                                   \
            const int row = c >> 2, cb = (c & 3) << 4;                            \
            const char* srcb = (j < 2) ? ah_g : (j < 4) ? al_g                    \
                               : (j < 6) ? bh_g : bl_g;                           \
            cp16(sb + (s) * STAGE_B + (j >> 1) * TILE_B + row * (LDT * 2) + cb,   \
                 srcb + (size_t)row * (D_ * 2) + d0b + cb);                       \
        }                                                                         \
        cp_commit();                                                              \
    } while (0)

    float cacc[4][4][4];
#pragma unroll
    for (int mt = 0; mt < 4; mt++)
#pragma unroll
        for (int nt = 0; nt < 4; nt++)
#pragma unroll
            for (int q = 0; q < 4; q++) cacc[mt][nt][q] = 0.f;

    // ldmatrix lane-address byte offsets within a tile
    const uint32_t a_lm = (uint32_t)(((wm * 64 + (lane & 15)) * LDT + (lane >> 4) * 8) * 2);
    const uint32_t b_lm = (uint32_t)(((wn * 32 + (lane & 7) + ((lane >> 4) << 3)) * LDT +
                                      (((lane >> 3) & 1) * 8)) * 2);

    // ---- prologue ----
    CP_STAGE(0, 0);
    CP_STAGE(1, 1);

    // ---- main loop ----
    for (int kt = 0; kt < NKT; kt++) {
        const int cur = kt & 1;
        if (kt + 1 < NKT) cp_wait<1>(); else cp_wait<0>();
        __syncthreads();

        const uint32_t stg = sb + cur * STAGE_B;
        const uint32_t baseAh = stg + a_lm;
        const uint32_t baseAl = stg + TILE_B + a_lm;
        const uint32_t baseBh = stg + 2 * TILE_B + b_lm;
        const uint32_t baseBl = stg + 3 * TILE_B + b_lm;
#pragma unroll
        for (int ks = 0; ks < 2; ks++) {
            const uint32_t ko = ks * 32;  // 16 bf16 * 2 B
            uint32_t bh[4][2], bo[4][2];
#pragma unroll
            for (int nt2 = 0; nt2 < 2; nt2++) {
                uint32_t t[4];
                ldsm4(t, baseBh + nt2 * (16 * LDT * 2) + ko);
                bh[nt2 * 2][0] = t[0]; bh[nt2 * 2][1] = t[1];
                bh[nt2 * 2 + 1][0] = t[2]; bh[nt2 * 2 + 1][1] = t[3];
                ldsm4(t, baseBl + nt2 * (16 * LDT * 2) + ko);
                bo[nt2 * 2][0] = t[0]; bo[nt2 * 2][1] = t[1];
                bo[nt2 * 2 + 1][0] = t[2]; bo[nt2 * 2 + 1][1] = t[3];
            }
#pragma unroll
            for (int mt = 0; mt < 4; mt++) {
                uint32_t ah[4], al[4];
                ldsm4(ah, baseAh + mt * (16 * LDT * 2) + ko);
                ldsm4(al, baseAl + mt * (16 * LDT * 2) + ko);
#pragma unroll
                for (int nt = 0; nt < 4; nt++) {
                    mma16816(cacc[mt][nt], ah, bh[nt]);
                    mma16816(cacc[mt][nt], ah, bo[nt]);
                    mma16816(cacc[mt][nt], al, bh[nt]);
                }
            }
        }
        __syncthreads();
        if (kt + 2 < NKT) CP_STAGE(cur, kt + 2);
    }

    // ---- epilogue: + t2h[i] + t2d[o] + bias[l] ----
    const float* t2h = g_t2h + (size_t)bl * S_;
    const float* t2d = g_t2d + (size_t)bl * S_;
    const float bz = bias[l];
    float* obase = out + (size_t)bl * S_ * S_;
#pragma unroll
    for (int mt = 0; mt < 4; mt++) {
        const int i_lo = i0 + wm * 64 + mt * 16 + (lane >> 2);
        const float ai0 = t2h[i_lo] + bz;
        const float ai1 = t2h[i_lo + 8] + bz;
        float* row0 = obase + (size_t)i_lo * S_;
        float* row1 = row0 + 8 * S_;
#pragma unroll
        for (int nt = 0; nt < 4; nt++) {
            const int o_ = o0 + wn * 32 + nt * 8 + (lane & 3) * 2;
            const float td0 = t2d[o_], td1 = t2d[o_ + 1];
            *(float2*)(row0 + o_) =
                make_float2(cacc[mt][nt][0] + td0 + ai0, cacc[mt][nt][1] + td1 + ai0);
            *(float2*)(row1 + o_) =
                make_float2(cacc[mt][nt][2] + td0 + ai1, cacc[mt][nt][3] + td1 + ai1);
        }
    }
#undef CP_STAGE
}

// ---------------------------------------------------------------------------
extern "C" void kernel_launch(void* const* d_in, const int* in_sizes, int n_in,
                              void* d_out, int out_size) {
    const float* head = (const float*)d_in[0];  // (B,S,D)
    const float* dep  = (const float*)d_in[1];  // (B,S,D)
    const float* U    = (const float*)d_in[2];  // (L,D)
    const float* W    = (const float*)d_in[3];  // (L,2D)
    const float* bias = (const float*)d_in[4];  // (L,)
    float* out = (float*)d_out;                 // (B,L,S,S)

    // Idempotent, unconditional (no static-state guards per harness rules).
    cudaFuncSetAttribute(biaffine_mma_kernel,
                         cudaFuncAttributeMaxDynamicSharedMemorySize, SMEM_TOTAL);

    split_dep_kernel<<<(B_ * S_ * D_ / 4) / 256, 256>>>(dep);
    prep_a_kernel<<<dim3(S_ * D_ / 4 / 256, B_ * L_), 256>>>(head, U);
    t2_kernel<<<B_ * L_, 256>>>(head, dep, W);

    // x enumerates the 16 (i,o) tiles of one (b,l): A/B slices stay L2-hot.
    dim3 grid(16, 1, B_ * L_);
    biaffine_mma_kernel<<<grid, 256, SMEM_TOTAL>>>(bias, out);
}

// round 7
// speedup vs baseline: 2.7785x; 1.4312x over previous
#include <cuda_runtime.h>
#include <cuda_fp16.h>
#include <cstdint>

#define B_ 4
#define S_ 512
#define D_ 768
#define L_ 64

// ---------------------------------------------------------------------------
// Global scratch (static __device__ arrays — allocation-free at launch time)
// ---------------------------------------------------------------------------
__device__ float g_t2h[B_ * L_ * S_];
__device__ float g_t2d[B_ * L_ * S_];
__device__ __half g_dep_hi[B_ * S_ * D_];                // 3 MB
__device__ __half g_dep_lo[B_ * S_ * D_];                // 3 MB
__device__ __half g_a[(size_t)B_ * L_ * S_ * D_];        // 201 MB (single fp16)

// ---------------------------------------------------------------------------
// PTX helpers (baseline sm_80-class — legal at compute_103)
// ---------------------------------------------------------------------------
__device__ __forceinline__ uint32_t smem_to_u32(const void* p) {
    uint32_t a;
    asm("{ .reg .u64 t; cvta.to.shared.u64 t, %1; cvt.u32.u64 %0, t; }" : "=r"(a) : "l"(p));
    return a;
}
__device__ __forceinline__ void cp16(uint32_t dst, const void* src) {
    asm volatile("cp.async.cg.shared.global [%0], [%1], 16;" :: "r"(dst), "l"(src));
}
__device__ __forceinline__ void cp_commit() {
    asm volatile("cp.async.commit_group;" ::: "memory");
}
template <int N> __device__ __forceinline__ void cp_wait() {
    asm volatile("cp.async.wait_group %0;" :: "n"(N) : "memory");
}
__device__ __forceinline__ void ldsm4(uint32_t r[4], uint32_t addr) {
    asm volatile("ldmatrix.sync.aligned.m8n8.x4.shared.b16 {%0,%1,%2,%3}, [%4];"
                 : "=r"(r[0]), "=r"(r[1]), "=r"(r[2]), "=r"(r[3]) : "r"(addr));
}
__device__ __forceinline__ void mma16816(float c[4], const uint32_t a[4], const uint32_t b[2]) {
    asm volatile("mma.sync.aligned.m16n8k16.row.col.f32.f16.f16.f32 "
                 "{%0,%1,%2,%3}, {%4,%5,%6,%7}, {%8,%9}, {%0,%1,%2,%3};"
                 : "+f"(c[0]), "+f"(c[1]), "+f"(c[2]), "+f"(c[3])
                 : "r"(a[0]), "r"(a[1]), "r"(a[2]), "r"(a[3]), "r"(b[0]), "r"(b[1]));
}
__device__ __forceinline__ uint32_t ph2(float a, float b) {
    __half2 t = __floats2half2_rn(a, b);
    return *(uint32_t*)&t;
}

// ---------------------------------------------------------------------------
// Prep 1: split dep into fp16 hi/lo
// ---------------------------------------------------------------------------
__global__ void split_dep_kernel(const float* __restrict__ dep) {
    int idx = blockIdx.x * blockDim.x + threadIdx.x;  // one float4 per thread
    float4 v = ((const float4*)dep)[idx];
    float f[4] = {v.x, v.y, v.z, v.w};
    float r[4];
#pragma unroll
    for (int q = 0; q < 4; q++)
        r[q] = f[q] - __half2float(__float2half_rn(f[q]));
    ((uint2*)g_dep_hi)[idx] = make_uint2(ph2(f[0], f[1]), ph2(f[2], f[3]));
    ((uint2*)g_dep_lo)[idx] = make_uint2(ph2(r[0], r[1]), ph2(r[2], r[3]));
}

// ---------------------------------------------------------------------------
// Prep 2: A[bl,i,d] = fp16( head[b,i,d] * U[l,d] )   — l-inner, head read once
// grid: ( S*D/4/256 = 384, B ), block 256
// ---------------------------------------------------------------------------
__global__ void prep_a_kernel(const float* __restrict__ head,
                              const float* __restrict__ U) {
    const int b = blockIdx.y;
    const int idx = blockIdx.x * 256 + threadIdx.x;   // 0 .. S*D/4-1
    const float4 h = ((const float4*)head)[(size_t)b * (S_ * D_ / 4) + idx];
    const int d4 = idx % (D_ / 4);
    const float4* Uf4 = (const float4*)U;
    uint2* dst = (uint2*)g_a + (size_t)b * L_ * (S_ * D_ / 4) + idx;
#pragma unroll 4
    for (int l = 0; l < L_; l++) {
        float4 u = Uf4[l * (D_ / 4) + d4];
        dst[(size_t)l * (S_ * D_ / 4)] =
            make_uint2(ph2(h.x * u.x, h.y * u.y), ph2(h.z * u.z, h.w * u.w));
    }
}

// ---------------------------------------------------------------------------
// Prep 3: rank-1 terms
// ---------------------------------------------------------------------------
__global__ void t2_kernel(const float* __restrict__ head,
                          const float* __restrict__ dep,
                          const float* __restrict__ W) {
    int bl = blockIdx.x;
    int b = bl / L_, l = bl % L_;
    int warp = threadIdx.x >> 5, lane = threadIdx.x & 31;
    const float* Wh = W + (size_t)l * (2 * D_);
    const float* Wd = Wh + D_;
    for (int i = warp; i < S_; i += 8) {
        const float* hr = head + ((size_t)b * S_ + i) * D_;
        const float* dr = dep + ((size_t)b * S_ + i) * D_;
        float sh = 0.f, sd = 0.f;
#pragma unroll 4
        for (int d = lane; d < D_; d += 32) {
            sh += hr[d] * Wh[d];
            sd += dr[d] * Wd[d];
        }
#pragma unroll
        for (int off = 16; off; off >>= 1) {
            sh += __shfl_down_sync(0xffffffffu, sh, off);
            sd += __shfl_down_sync(0xffffffffu, sd, off);
        }
        if (lane == 0) {
            g_t2h[(size_t)bl * S_ + i] = sh;
            g_t2d[(size_t)bl * S_ + i] = sd;
        }
    }
}

// ---------------------------------------------------------------------------
// Main GEMM: C = A·Bh^T + A·Bl^T  (A fp16, B fp16 hi/lo, fp32 accum)
// 128x128 CTA tile, BK=32, 8 warps (2m x 4n, warp tile 64x32),
// 3-stage cp.async pipeline, 2 CTAs/SM.
// Dynamic smem: 3 stages x 3 tiles (A,Bh,Bl) x 10240 B = 92160 B.
// ---------------------------------------------------------------------------
#define BK 32
#define NKT (D_ / BK) /* 24 */
#define LDT 40
#define TILE_B 10240
#define STAGE_B 30720
#define NSTG 3
#define SMEM_TOTAL 92160

__global__ __launch_bounds__(256, 2)
void biaffine_mma_kernel(const float* __restrict__ bias,
                         float* __restrict__ out) {
    extern __shared__ __align__(16) char smem[];
    const uint32_t sb = smem_to_u32(smem);

    const int tid = threadIdx.x;
    const int wid = tid >> 5, lane = tid & 31;
    const int wm = wid & 1, wn = wid >> 1;
    const int bl = blockIdx.z;
    const int b = bl >> 6, l = bl & (L_ - 1);
    const int i0 = (blockIdx.x >> 2) * 128;
    const int o0 = (blockIdx.x & 3) * 128;

    const char* a_g  = (const char*)(g_a + ((size_t)bl * S_ + i0) * D_);
    const char* bh_g = (const char*)(g_dep_hi + ((size_t)b * S_ + o0) * D_);
    const char* bl_g = (const char*)(g_dep_lo + ((size_t)b * S_ + o0) * D_);

#define CP_STAGE(s, kt)                                                           \
    do {                                                                          \
        const int d0b = (kt) * (BK * 2);                                          \
        _Pragma("unroll") for (int j = 0; j < 6; j++) {                           \
            const int c = ((j & 1) << 8) | tid;                                   \
            const int row = c >> 2, cb = (c & 3) << 4;                            \
            const char* srcb = (j < 2) ? a_g : (j < 4) ? bh_g : bl_g;             \
            cp16(sb + (s) * STAGE_B + (j >> 1) * TILE_B + row * (LDT * 2) + cb,   \
                 srcb + (size_t)row * (D_ * 2) + d0b + cb);                       \
        }                                                                         \
        cp_commit();                                                              \
    } while (0)

    float cacc[4][4][4];
#pragma unroll
    for (int mt = 0; mt < 4; mt++)
#pragma unroll
        for (int nt = 0; nt < 4; nt++)
#pragma unroll
            for (int q = 0; q < 4; q++) cacc[mt][nt][q] = 0.f;

    // ldmatrix lane-address byte offsets within a tile
    const uint32_t a_lm = (uint32_t)(((wm * 64 + (lane & 15)) * LDT + (lane >> 4) * 8) * 2);
    const uint32_t b_lm = (uint32_t)(((wn * 32 + (lane & 7) + ((lane >> 4) << 3)) * LDT +
                                      (((lane >> 3) & 1) * 8)) * 2);

    // ---- prologue: fill 3 stages ----
    CP_STAGE(0, 0);
    CP_STAGE(1, 1);
    CP_STAGE(2, 2);

    // ---- main loop ----
    int stg_i = 0;
    for (int kt = 0; kt < NKT; kt++) {
        const int rem = NKT - 1 - kt;
        if (rem >= 2) cp_wait<2>();
        else if (rem == 1) cp_wait<1>();
        else cp_wait<0>();
        __syncthreads();

        const uint32_t stg = sb + stg_i * STAGE_B;
        const uint32_t baseA  = stg + a_lm;
        const uint32_t baseBh = stg + TILE_B + b_lm;
        const uint32_t baseBl = stg + 2 * TILE_B + b_lm;
#pragma unroll
        for (int ks = 0; ks < 2; ks++) {
            const uint32_t ko = ks * 32;  // 16 fp16 * 2 B
            uint32_t bh[4][2], bo[4][2];
#pragma unroll
            for (int nt2 = 0; nt2 < 2; nt2++) {
                uint32_t t[4];
                ldsm4(t, baseBh + nt2 * (16 * LDT * 2) + ko);
                bh[nt2 * 2][0] = t[0]; bh[nt2 * 2][1] = t[1];
                bh[nt2 * 2 + 1][0] = t[2]; bh[nt2 * 2 + 1][1] = t[3];
                ldsm4(t, baseBl + nt2 * (16 * LDT * 2) + ko);
                bo[nt2 * 2][0] = t[0]; bo[nt2 * 2][1] = t[1];
                bo[nt2 * 2 + 1][0] = t[2]; bo[nt2 * 2 + 1][1] = t[3];
            }
#pragma unroll
            for (int mt = 0; mt < 4; mt++) {
                uint32_t ah[4];
                ldsm4(ah, baseA + mt * (16 * LDT * 2) + ko);
#pragma unroll
                for (int nt = 0; nt < 4; nt++) {
                    mma16816(cacc[mt][nt], ah, bh[nt]);
                    mma16816(cacc[mt][nt], ah, bo[nt]);
                }
            }
        }
        __syncthreads();
        if (kt + NSTG < NKT) CP_STAGE(stg_i, kt + NSTG);
        if (++stg_i == NSTG) stg_i = 0;
    }

    // ---- epilogue: + t2h[i] + t2d[o] + bias[l] ----
    const float* t2h = g_t2h + (size_t)bl * S_;
    const float* t2d = g_t2d + (size_t)bl * S_;
    const float bz = bias[l];
    float* obase = out + (size_t)bl * S_ * S_;
#pragma unroll
    for (int mt = 0; mt < 4; mt++) {
        const int i_lo = i0 + wm * 64 + mt * 16 + (lane >> 2);
        const float ai0 = t2h[i_lo] + bz;
        const float ai1 = t2h[i_lo + 8] + bz;
        float* row0 = obase + (size_t)i_lo * S_;
        float* row1 = row0 + 8 * S_;
#pragma unroll
        for (int nt = 0; nt < 4; nt++) {
            const int o_ = o0 + wn * 32 + nt * 8 + (lane & 3) * 2;
            const float td0 = t2d[o_], td1 = t2d[o_ + 1];
            *(float2*)(row0 + o_) =
                make_float2(cacc[mt][nt][0] + td0 + ai0, cacc[mt][nt][1] + td1 + ai0);
            *(float2*)(row1 + o_) =
                make_float2(cacc[mt][nt][2] + td0 + ai1, cacc[mt][nt][3] + td1 + ai1);
        }
    }
#undef CP_STAGE
}

// ---------------------------------------------------------------------------
extern "C" void kernel_launch(void* const* d_in, const int* in_sizes, int n_in,
                              void* d_out, int out_size) {
    const float* head = (const float*)d_in[0];  // (B,S,D)
    const float* dep  = (const float*)d_in[1];  // (B,S,D)
    const float* U    = (const float*)d_in[2];  // (L,D)
    const float* W    = (const float*)d_in[3];  // (L,2D)
    const float* bias = (const float*)d_in[4];  // (L,)
    float* out = (float*)d_out;                 // (B,L,S,S)

    cudaFuncSetAttribute(biaffine_mma_kernel,
                         cudaFuncAttributeMaxDynamicSharedMemorySize, SMEM_TOTAL);

    split_dep_kernel<<<(B_ * S_ * D_ / 4) / 256, 256>>>(dep);
    prep_a_kernel<<<dim3(S_ * D_ / 4 / 256, B_), 256>>>(head, U);
    t2_kernel<<<B_ * L_, 256>>>(head, dep, W);

    // x enumerates the 16 (i,o) tiles of one (b,l): A/B slices stay L2-hot.
    dim3 grid(16, 1, B_ * L_);
    biaffine_mma_kernel<<<grid, 256, SMEM_TOTAL>>>(bias, out);
}

// round 8
// speedup vs baseline: 5.4655x; 1.9670x over previous
#include <cuda_runtime.h>
#include <cuda_fp16.h>
#include <cstdint>

#define B_ 4
#define S_ 512
#define D_ 768
#define L_ 64

// ---------------------------------------------------------------------------
// Global scratch (static __device__ arrays — allocation-free at launch time)
// ---------------------------------------------------------------------------
__device__ float g_t2h[B_ * L_ * S_];
__device__ float g_t2d[B_ * L_ * S_];
__device__ __half g_head_h[B_ * S_ * D_];          // 3 MB
__device__ __half g_dep_h[B_ * S_ * D_];           // 3 MB
__device__ __half g_u_h[L_ * D_];                  // 96 KB
__device__ __half g_a[(size_t)B_ * L_ * S_ * D_];  // 201 MB

// ---------------------------------------------------------------------------
// PTX helpers (baseline sm_80-class — legal at compute_103)
// ---------------------------------------------------------------------------
__device__ __forceinline__ uint32_t smem_to_u32(const void* p) {
    uint32_t a;
    asm("{ .reg .u64 t; cvta.to.shared.u64 t, %1; cvt.u32.u64 %0, t; }" : "=r"(a) : "l"(p));
    return a;
}
__device__ __forceinline__ void cp16(uint32_t dst, const void* src) {
    asm volatile("cp.async.cg.shared.global [%0], [%1], 16;" :: "r"(dst), "l"(src));
}
__device__ __forceinline__ void cp_commit() {
    asm volatile("cp.async.commit_group;" ::: "memory");
}
template <int N> __device__ __forceinline__ void cp_wait() {
    asm volatile("cp.async.wait_group %0;" :: "n"(N) : "memory");
}
__device__ __forceinline__ void ldsm4(uint32_t r[4], uint32_t addr) {
    asm volatile("ldmatrix.sync.aligned.m8n8.x4.shared.b16 {%0,%1,%2,%3}, [%4];"
                 : "=r"(r[0]), "=r"(r[1]), "=r"(r[2]), "=r"(r[3]) : "r"(addr));
}
__device__ __forceinline__ void mma16816(float c[4], const uint32_t a[4], const uint32_t b[2]) {
    asm volatile("mma.sync.aligned.m16n8k16.row.col.f32.f16.f16.f32 "
                 "{%0,%1,%2,%3}, {%4,%5,%6,%7}, {%8,%9}, {%0,%1,%2,%3};"
                 : "+f"(c[0]), "+f"(c[1]), "+f"(c[2]), "+f"(c[3])
                 : "r"(a[0]), "r"(a[1]), "r"(a[2]), "r"(a[3]), "r"(b[0]), "r"(b[1]));
}
__device__ __forceinline__ uint32_t ph2(float a, float b) {
    __half2 t = __floats2half2_rn(a, b);
    return *(uint32_t*)&t;
}
__device__ __forceinline__ uint32_t hm2(uint32_t a, uint32_t b) {
    __half2 x = *(__half2*)&a, y = *(__half2*)&b;
    __half2 z = __hmul2(x, y);
    return *(uint32_t*)&z;
}

// ---------------------------------------------------------------------------
// Prep 0: fp32 -> fp16 conversion (dst selected by flag; 3 launches)
// ---------------------------------------------------------------------------
__global__ void cvt_half_kernel(const float* __restrict__ src, int dst_sel) {
    __half* dst = (dst_sel == 0) ? g_head_h : (dst_sel == 1) ? g_dep_h : g_u_h;
    int idx = blockIdx.x * blockDim.x + threadIdx.x;  // one float4 per thread
    float4 v = ((const float4*)src)[idx];
    ((uint2*)dst)[idx] = make_uint2(ph2(v.x, v.y), ph2(v.z, v.w));
}

// ---------------------------------------------------------------------------
// Prep 1: A[bl,i,d] = g_head_h[b,i,d] * g_u_h[l,d]  (HMUL2, 16 elems/thread)
// grid: ( S*D/16/256 = 96, B ), block 256
// ---------------------------------------------------------------------------
__global__ void prep_a_kernel() {
    const int b = blockIdx.y;
    const int idx = blockIdx.x * 256 + threadIdx.x;  // 0 .. S*D/16-1
    const int nd16 = D_ / 16;                        // 48
    const int d16 = idx % nd16, i = idx / nd16;
    const uint4* hp = (const uint4*)(g_head_h + ((size_t)b * S_ + i) * D_ + d16 * 16);
    const uint4 h0 = hp[0], h1 = hp[1];
    __half* dst0 = g_a + ((size_t)(b * L_) * S_ + i) * D_ + d16 * 16;
#pragma unroll 4
    for (int l = 0; l < L_; l++) {
        const uint4* up = (const uint4*)(g_u_h + (size_t)l * D_ + d16 * 16);
        uint4 u0 = up[0], u1 = up[1];
        uint4 r0 = make_uint4(hm2(h0.x, u0.x), hm2(h0.y, u0.y),
                              hm2(h0.z, u0.z), hm2(h0.w, u0.w));
        uint4 r1 = make_uint4(hm2(h1.x, u1.x), hm2(h1.y, u1.y),
                              hm2(h1.z, u1.z), hm2(h1.w, u1.w));
        uint4* dp = (uint4*)(dst0 + (size_t)l * (S_ * D_));
        dp[0] = r0;
        dp[1] = r1;
    }
}

// ---------------------------------------------------------------------------
// Prep 2: rank-1 terms. Block = 8 rows of one batch; rows live in registers,
// W streamed with float4 loads (L2-hot). grid B*S/8 = 256, block 256.
// ---------------------------------------------------------------------------
__global__ void t2_kernel(const float* __restrict__ head,
                          const float* __restrict__ dep,
                          const float* __restrict__ W) {
    const int b = blockIdx.x >> 6;
    const int i = (blockIdx.x & 63) * 8 + (threadIdx.x >> 5);
    const int lane = threadIdx.x & 31;
    const float4* hr = (const float4*)(head + ((size_t)b * S_ + i) * D_);
    const float4* dr = (const float4*)(dep + ((size_t)b * S_ + i) * D_);
    float4 hreg[6], dreg[6];
#pragma unroll
    for (int q = 0; q < 6; q++) {
        hreg[q] = hr[lane + q * 32];
        dreg[q] = dr[lane + q * 32];
    }
    for (int l = 0; l < L_; l++) {
        const float4* Wh = (const float4*)(W + (size_t)l * (2 * D_));
        const float4* Wd = (const float4*)(W + (size_t)l * (2 * D_) + D_);
        float sh = 0.f, sd = 0.f;
#pragma unroll
        for (int q = 0; q < 6; q++) {
            float4 wh = Wh[lane + q * 32], wd = Wd[lane + q * 32];
            sh += hreg[q].x * wh.x + hreg[q].y * wh.y + hreg[q].z * wh.z + hreg[q].w * wh.w;
            sd += dreg[q].x * wd.x + dreg[q].y * wd.y + dreg[q].z * wd.z + dreg[q].w * wd.w;
        }
#pragma unroll
        for (int off = 16; off; off >>= 1) {
            sh += __shfl_down_sync(0xffffffffu, sh, off);
            sd += __shfl_down_sync(0xffffffffu, sd, off);
        }
        if (lane == 0) {
            g_t2h[((size_t)b * L_ + l) * S_ + i] = sh;
            g_t2d[((size_t)b * L_ + l) * S_ + i] = sd;
        }
    }
}

// ---------------------------------------------------------------------------
// Main GEMM: C = A·B^T  (single-pass fp16, fp32 accum)
// 128x128 CTA tile, BK=32, 8 warps (2m x 4n, warp tile 64x32),
// 4-stage cp.async pipeline, ONE __syncthreads per k-iter, 2 CTAs/SM.
// Dynamic smem: 4 stages x 2 tiles (A,B) x 10240 B = 81920 B.
// ---------------------------------------------------------------------------
#define BK 32
#define NKT (D_ / BK) /* 24 */
#define LDT 40
#define TILE_B 10240
#define STAGE_B 20480
#define NSTG 4
#define SMEM_TOTAL 81920

__global__ __launch_bounds__(256, 2)
void biaffine_mma_kernel(const float* __restrict__ bias,
                         float* __restrict__ out) {
    extern __shared__ __align__(16) char smem[];
    const uint32_t sb = smem_to_u32(smem);

    const int tid = threadIdx.x;
    const int wid = tid >> 5, lane = tid & 31;
    const int wm = wid & 1, wn = wid >> 1;
    const int bl = blockIdx.z;
    const int b = bl >> 6, l = bl & (L_ - 1);
    const int i0 = (blockIdx.x >> 2) * 128;
    const int o0 = (blockIdx.x & 3) * 128;

    const char* a_g = (const char*)(g_a + ((size_t)bl * S_ + i0) * D_);
    const char* b_g = (const char*)(g_dep_h + ((size_t)b * S_ + o0) * D_);

#define CP_STAGE(s, kt)                                                           \
    do {                                                                          \
        const int d0b = (kt) * (BK * 2);                                          \
        _Pragma("unroll") for (int j = 0; j < 4; j++) {                           \
            const int c = ((j & 1) << 8) | tid;                                   \
            const int row = c >> 2, cb = (c & 3) << 4;                            \
            const char* srcb = (j < 2) ? a_g : b_g;                               \
            cp16(sb + (s) * STAGE_B + (j >> 1) * TILE_B + row * (LDT * 2) + cb,   \
                 srcb + (size_t)row * (D_ * 2) + d0b + cb);                       \
        }                                                                         \
        cp_commit();                                                              \
    } while (0)

    float cacc[4][4][4];
#pragma unroll
    for (int mt = 0; mt < 4; mt++)
#pragma unroll
        for (int nt = 0; nt < 4; nt++)
#pragma unroll
            for (int q = 0; q < 4; q++) cacc[mt][nt][q] = 0.f;

    // ldmatrix lane-address byte offsets within a tile
    const uint32_t a_lm = (uint32_t)(((wm * 64 + (lane & 15)) * LDT + (lane >> 4) * 8) * 2);
    const uint32_t b_lm = (uint32_t)(((wn * 32 + (lane & 7) + ((lane >> 4) << 3)) * LDT +
                                      (((lane >> 3) & 1) * 8)) * 2);

    // ---- prologue: fill NSTG-1 = 3 stages ----
    CP_STAGE(0, 0);
    CP_STAGE(1, 1);
    CP_STAGE(2, 2);

    // ---- main loop: one sync per iteration ----
    for (int kt = 0; kt < NKT; kt++) {
        const int rem = NKT - 1 - kt;
        if (rem >= 2) cp_wait<2>();
        else if (rem == 1) cp_wait<1>();
        else cp_wait<0>();
        __syncthreads();
        // Refill the stage consumed LAST iteration (safe: all warps passed it).
        if (kt + NSTG - 1 < NKT) CP_STAGE((kt + NSTG - 1) & (NSTG - 1), kt + NSTG - 1);

        const uint32_t stg = sb + (kt & (NSTG - 1)) * STAGE_B;
        const uint32_t baseA = stg + a_lm;
        const uint32_t baseB = stg + TILE_B + b_lm;
#pragma unroll
        for (int ks = 0; ks < 2; ks++) {
            const uint32_t ko = ks * 32;  // 16 fp16 * 2 B
            uint32_t bh[4][2];
#pragma unroll
            for (int nt2 = 0; nt2 < 2; nt2++) {
                uint32_t t[4];
                ldsm4(t, baseB + nt2 * (16 * LDT * 2) + ko);
                bh[nt2 * 2][0] = t[0]; bh[nt2 * 2][1] = t[1];
                bh[nt2 * 2 + 1][0] = t[2]; bh[nt2 * 2 + 1][1] = t[3];
            }
#pragma unroll
            for (int mt = 0; mt < 4; mt++) {
                uint32_t ah[4];
                ldsm4(ah, baseA + mt * (16 * LDT * 2) + ko);
#pragma unroll
                for (int nt = 0; nt < 4; nt++) mma16816(cacc[mt][nt], ah, bh[nt]);
            }
        }
    }

    // ---- epilogue: + t2h[i] + t2d[o] + bias[l] ----
    const float* t2h = g_t2h + (size_t)bl * S_;
    const float* t2d = g_t2d + (size_t)bl * S_;
    const float bz = bias[l];
    float* obase = out + (size_t)bl * S_ * S_;
#pragma unroll
    for (int mt = 0; mt < 4; mt++) {
        const int i_lo = i0 + wm * 64 + mt * 16 + (lane >> 2);
        const float ai0 = t2h[i_lo] + bz;
        const float ai1 = t2h[i_lo + 8] + bz;
        float* row0 = obase + (size_t)i_lo * S_;
        float* row1 = row0 + 8 * S_;
#pragma unroll
        for (int nt = 0; nt < 4; nt++) {
            const int o_ = o0 + wn * 32 + nt * 8 + (lane & 3) * 2;
            const float td0 = t2d[o_], td1 = t2d[o_ + 1];
            *(float2*)(row0 + o_) =
                make_float2(cacc[mt][nt][0] + td0 + ai0, cacc[mt][nt][1] + td1 + ai0);
            *(float2*)(row1 + o_) =
                make_float2(cacc[mt][nt][2] + td0 + ai1, cacc[mt][nt][3] + td1 + ai1);
        }
    }
#undef CP_STAGE
}

// ---------------------------------------------------------------------------
extern "C" void kernel_launch(void* const* d_in, const int* in_sizes, int n_in,
                              void* d_out, int out_size) {
    const float* head = (const float*)d_in[0];  // (B,S,D)
    const float* dep  = (const float*)d_in[1];  // (B,S,D)
    const float* U    = (const float*)d_in[2];  // (L,D)
    const float* W    = (const float*)d_in[3];  // (L,2D)
    const float* bias = (const float*)d_in[4];  // (L,)
    float* out = (float*)d_out;                 // (B,L,S,S)

    cudaFuncSetAttribute(biaffine_mma_kernel,
                         cudaFuncAttributeMaxDynamicSharedMemorySize, SMEM_TOTAL);

    cvt_half_kernel<<<(B_ * S_ * D_ / 4) / 256, 256>>>(head, 0);
    cvt_half_kernel<<<(B_ * S_ * D_ / 4) / 256, 256>>>(dep, 1);
    cvt_half_kernel<<<(L_ * D_ / 4) / 256, 256>>>(U, 2);
    prep_a_kernel<<<dim3(S_ * D_ / 16 / 256, B_), 256>>>();
    t2_kernel<<<B_ * S_ / 8, 256>>>(head, dep, W);

    // x enumerates the 16 (i,o) tiles of one (b,l): A/B slices stay L2-hot.
    dim3 grid(16, 1, B_ * L_);
    biaffine_mma_kernel<<<grid, 256, SMEM_TOTAL>>>(bias, out);
}

// round 10
// speedup vs baseline: 6.3122x; 1.1549x over previous
#include <cuda_runtime.h>
#include <cuda_fp16.h>
#include <cstdint>

#define B_ 4
#define S_ 512
#define D_ 768
#define L_ 64

// ---------------------------------------------------------------------------
// Global scratch (static __device__ arrays — allocation-free at launch time)
// ---------------------------------------------------------------------------
__device__ float g_t2h[B_ * L_ * S_];
__device__ float g_t2d[B_ * L_ * S_];
__device__ __half g_head_h[B_ * S_ * D_];  // 3 MB
__device__ __half g_dep_h[B_ * S_ * D_];   // 3 MB
__device__ __half g_u_h[L_ * D_];          // 96 KB

// ---------------------------------------------------------------------------
// PTX helpers (baseline sm_80-class — legal at compute_103)
// ---------------------------------------------------------------------------
__device__ __forceinline__ uint32_t smem_to_u32(const void* p) {
    uint32_t a;
    asm("{ .reg .u64 t; cvta.to.shared.u64 t, %1; cvt.u32.u64 %0, t; }" : "=r"(a) : "l"(p));
    return a;
}
__device__ __forceinline__ void cp16(uint32_t dst, const void* src) {
    asm volatile("cp.async.cg.shared.global [%0], [%1], 16;" :: "r"(dst), "l"(src));
}
__device__ __forceinline__ void cp_commit() {
    asm volatile("cp.async.commit_group;" ::: "memory");
}
template <int N> __device__ __forceinline__ void cp_wait() {
    asm volatile("cp.async.wait_group %0;" :: "n"(N) : "memory");
}
__device__ __forceinline__ void ldsm4(uint32_t r[4], uint32_t addr) {
    asm volatile("ldmatrix.sync.aligned.m8n8.x4.shared.b16 {%0,%1,%2,%3}, [%4];"
                 : "=r"(r[0]), "=r"(r[1]), "=r"(r[2]), "=r"(r[3]) : "r"(addr));
}
__device__ __forceinline__ void mma16816(float c[4], const uint32_t a[4], const uint32_t b[2]) {
    asm volatile("mma.sync.aligned.m16n8k16.row.col.f32.f16.f16.f32 "
                 "{%0,%1,%2,%3}, {%4,%5,%6,%7}, {%8,%9}, {%0,%1,%2,%3};"
                 : "+f"(c[0]), "+f"(c[1]), "+f"(c[2]), "+f"(c[3])
                 : "r"(a[0]), "r"(a[1]), "r"(a[2]), "r"(a[3]), "r"(b[0]), "r"(b[1]));
}
__device__ __forceinline__ uint32_t ph2(float a, float b) {
    __half2 t = __floats2half2_rn(a, b);
    return *(uint32_t*)&t;
}
__device__ __forceinline__ uint32_t hm2(uint32_t a, uint32_t b) {
    __half2 x = *(__half2*)&a, y = *(__half2*)&b;
    __half2 z = __hmul2(x, y);
    return *(uint32_t*)&z;
}

// ---------------------------------------------------------------------------
// Prep 0: fp32 -> fp16 conversion (dst selected by flag; 3 launches)
// ---------------------------------------------------------------------------
__global__ void cvt_half_kernel(const float* __restrict__ src, int dst_sel) {
    __half* dst = (dst_sel == 0) ? g_head_h : (dst_sel == 1) ? g_dep_h : g_u_h;
    int idx = blockIdx.x * blockDim.x + threadIdx.x;  // one float4 per thread
    float4 v = ((const float4*)src)[idx];
    ((uint2*)dst)[idx] = make_uint2(ph2(v.x, v.y), ph2(v.z, v.w));
}

// ---------------------------------------------------------------------------
// Prep 1: rank-1 terms. Block = 8 rows of one batch; rows live in registers,
// W streamed with float4 loads (L2-hot). grid B*S/8 = 256, block 256.
// ---------------------------------------------------------------------------
__global__ void t2_kernel(const float* __restrict__ head,
                          const float* __restrict__ dep,
                          const float* __restrict__ W) {
    const int b = blockIdx.x >> 6;
    const int i = (blockIdx.x & 63) * 8 + (threadIdx.x >> 5);
    const int lane = threadIdx.x & 31;
    const float4* hr = (const float4*)(head + ((size_t)b * S_ + i) * D_);
    const float4* dr = (const float4*)(dep + ((size_t)b * S_ + i) * D_);
    float4 hreg[6], dreg[6];
#pragma unroll
    for (int q = 0; q < 6; q++) {
        hreg[q] = hr[lane + q * 32];
        dreg[q] = dr[lane + q * 32];
    }
    for (int l = 0; l < L_; l++) {
        const float4* Wh = (const float4*)(W + (size_t)l * (2 * D_));
        const float4* Wd = (const float4*)(W + (size_t)l * (2 * D_) + D_);
        float sh = 0.f, sd = 0.f;
#pragma unroll
        for (int q = 0; q < 6; q++) {
            float4 wh = Wh[lane + q * 32], wd = Wd[lane + q * 32];
            sh += hreg[q].x * wh.x + hreg[q].y * wh.y + hreg[q].z * wh.z + hreg[q].w * wh.w;
            sd += dreg[q].x * wd.x + dreg[q].y * wd.y + dreg[q].z * wd.z + dreg[q].w * wd.w;
        }
#pragma unroll
        for (int off = 16; off; off >>= 1) {
            sh += __shfl_down_sync(0xffffffffu, sh, off);
            sd += __shfl_down_sync(0xffffffffu, sd, off);
        }
        if (lane == 0) {
            g_t2h[((size_t)b * L_ + l) * S_ + i] = sh;
            g_t2d[((size_t)b * L_ + l) * S_ + i] = sd;
        }
    }
}

// ---------------------------------------------------------------------------
// Main GEMM: C = (head_h ⊙ U[l])·dep_h^T  (fp16 inputs, fp32 accum)
// A tiles produced IN-KERNEL: LDG head fp16 (L2-hot) -> HMUL2 with U[l]
// (fp16, staged in smem) -> STS swizzled. B via cp.async.
// 128x128 CTA tile, BK=32, 8 warps (2m x 4n, warp tile 64x32),
// 4-stage pipeline, ONE __syncthreads per k-iter, 2 CTAs/SM.
// Dynamic smem: 4 stages x (A 10240 + B 10240) + Us 1536 = 83456 B.
// ---------------------------------------------------------------------------
#define BK 32
#define NKT (D_ / BK) /* 24 */
#define LDT 40
#define TILE_B 10240
#define STAGE_B 20480
#define NSTG 4
#define OFF_US 81920
#define SMEM_TOTAL 83456

__global__ __launch_bounds__(256, 2)
void biaffine_mma_kernel(const float* __restrict__ bias,
                         float* __restrict__ out) {
    extern __shared__ __align__(16) char smem[];
    const uint32_t sb = smem_to_u32(smem);

    const int tid = threadIdx.x;
    const int wid = tid >> 5, lane = tid & 31;
    const int wm = wid & 1, wn = wid >> 1;
    const int bl = blockIdx.z;
    const int b = bl >> 6, l = bl & (L_ - 1);
    const int i0 = (blockIdx.x >> 2) * 128;
    const int o0 = (blockIdx.x & 3) * 128;

    // Stage U[l] (fp16) into smem: 768 halves = 96 uint4
    {
        const uint4* us = (const uint4*)(g_u_h + (size_t)l * D_);
        if (tid < 96) ((uint4*)(smem + OFF_US))[tid] = us[tid];
    }
    __syncthreads();

    const char* h_g = (const char*)(g_head_h + ((size_t)b * S_ + i0) * D_);
    const char* b_g = (const char*)(g_dep_h + ((size_t)b * S_ + o0) * D_);

    // Per-thread A production coordinates: j=0,1 -> c = j*256+tid (0..511)
    // row = c>>2 (0..127), col byte-offset cb = (c&3)*16 within 64-B chunk row.
    const int c0r = tid >> 2, c1r = (256 + tid) >> 2;  // c1r = c0r + 64
    const int cbi = (tid & 3) * 16;                    // byte offset (8 halves)

    uint4 apref[2];  // head chunk for the stage being produced next

#define LOAD_A_REGS(kt)                                                           \
    do {                                                                          \
        const int d0b = (kt) * (BK * 2);                                          \
        apref[0] = *(const uint4*)(h_g + (size_t)c0r * (D_ * 2) + d0b + cbi);     \
        apref[1] = *(const uint4*)(h_g + (size_t)c1r * (D_ * 2) + d0b + cbi);     \
    } while (0)

#define STORE_A(s, kt)                                                            \
    do {                                                                          \
        const int d0b = (kt) * (BK * 2);                                          \
        const uint4 uq = *(const uint4*)(smem + OFF_US + d0b + cbi);              \
        uint4 r0 = make_uint4(hm2(apref[0].x, uq.x), hm2(apref[0].y, uq.y),       \
                              hm2(apref[0].z, uq.z), hm2(apref[0].w, uq.w));      \
        uint4 r1 = make_uint4(hm2(apref[1].x, uq.x), hm2(apref[1].y, uq.y),       \
                              hm2(apref[1].z, uq.z), hm2(apref[1].w, uq.w));      \
        *(uint4*)(smem + (s) * STAGE_B + c0r * (LDT * 2) + cbi) = r0;             \
        *(uint4*)(smem + (s) * STAGE_B + c1r * (LDT * 2) + cbi) = r1;             \
    } while (0)

#define CP_B(s, kt)                                                               \
    do {                                                                          \
        const int d0b = (kt) * (BK * 2);                                          \
        cp16(sb + (s) * STAGE_B + TILE_B + c0r * (LDT * 2) + cbi,                 \
             b_g + (size_t)c0r * (D_ * 2) + d0b + cbi);                           \
        cp16(sb + (s) * STAGE_B + TILE_B + c1r * (LDT * 2) + cbi,                 \
             b_g + (size_t)c1r * (D_ * 2) + d0b + cbi);                           \
        cp_commit();                                                              \
    } while (0)

    float cacc[4][4][4];
#pragma unroll
    for (int mt = 0; mt < 4; mt++)
#pragma unroll
        for (int nt = 0; nt < 4; nt++)
#pragma unroll
            for (int q = 0; q < 4; q++) cacc[mt][nt][q] = 0.f;

    // ldmatrix lane-address byte offsets within a tile
    const uint32_t a_lm = (uint32_t)(((wm * 64 + (lane & 15)) * LDT + (lane >> 4) * 8) * 2);
    const uint32_t b_lm = (uint32_t)(((wn * 32 + (lane & 7) + ((lane >> 4) << 3)) * LDT +
                                      (((lane >> 3) & 1) * 8)) * 2);

    // ---- prologue: produce A + launch B for stages 0..2; prefetch A regs(3) ----
    LOAD_A_REGS(0);
    STORE_A(0, 0);
    CP_B(0, 0);
    LOAD_A_REGS(1);
    STORE_A(1, 1);
    CP_B(1, 1);
    LOAD_A_REGS(2);
    STORE_A(2, 2);
    CP_B(2, 2);
    LOAD_A_REGS(3);

    // ---- main loop: one sync per iteration ----
    for (int kt = 0; kt < NKT; kt++) {
        const int rem = NKT - 1 - kt;
        if (rem >= 2) cp_wait<2>();
        else if (rem == 1) cp_wait<1>();
        else cp_wait<0>();
        __syncthreads();
        // Produce stage kt+3 (consumed 3 iters from now; all warps passed its
        // last read at iter kt-1's barrier).
        if (kt + NSTG - 1 < NKT) {
            STORE_A((kt + NSTG - 1) & (NSTG - 1), kt + NSTG - 1);
            CP_B((kt + NSTG - 1) & (NSTG - 1), kt + NSTG - 1);
        }
        if (kt + NSTG < NKT) LOAD_A_REGS(kt + NSTG);

        const uint32_t stg = sb + (kt & (NSTG - 1)) * STAGE_B;
        const uint32_t baseA = stg + a_lm;
        const uint32_t baseB = stg + TILE_B + b_lm;
#pragma unroll
        for (int ks = 0; ks < 2; ks++) {
            const uint32_t ko = ks * 32;  // 16 fp16 * 2 B
            uint32_t bh[4][2];
#pragma unroll
            for (int nt2 = 0; nt2 < 2; nt2++) {
                uint32_t t[4];
                ldsm4(t, baseB + nt2 * (16 * LDT * 2) + ko);
                bh[nt2 * 2][0] = t[0]; bh[nt2 * 2][1] = t[1];
                bh[nt2 * 2 + 1][0] = t[2]; bh[nt2 * 2 + 1][1] = t[3];
            }
#pragma unroll
            for (int mt = 0; mt < 4; mt++) {
                uint32_t ah[4];
                ldsm4(ah, baseA + mt * (16 * LDT * 2) + ko);
#pragma unroll
                for (int nt = 0; nt < 4; nt++) mma16816(cacc[mt][nt], ah, bh[nt]);
            }
        }
    }

    // ---- epilogue: + t2h[i] + t2d[o] + bias[l] ----
    const float* t2h = g_t2h + (size_t)bl * S_;
    const float* t2d = g_t2d + (size_t)bl * S_;
    const float bz = bias[l];
    float* obase = out + (size_t)bl * S_ * S_;
#pragma unroll
    for (int mt = 0; mt < 4; mt++) {
        const int i_lo = i0 + wm * 64 + mt * 16 + (lane >> 2);
        const float ai0 = t2h[i_lo] + bz;
        const float ai1 = t2h[i_lo + 8] + bz;
        float* row0 = obase + (size_t)i_lo * S_;
        float* row1 = row0 + 8 * S_;
#pragma unroll
        for (int nt = 0; nt < 4; nt++) {
            const int o_ = o0 + wn * 32 + nt * 8 + (lane & 3) * 2;
            const float td0 = t2d[o_], td1 = t2d[o_ + 1];
            *(float2*)(row0 + o_) =
                make_float2(cacc[mt][nt][0] + td0 + ai0, cacc[mt][nt][1] + td1 + ai0);
            *(float2*)(row1 + o_) =
                make_float2(cacc[mt][nt][2] + td0 + ai1, cacc[mt][nt][3] + td1 + ai1);
        }
    }
#undef LOAD_A_REGS
#undef STORE_A
#undef CP_B
}

// ---------------------------------------------------------------------------
extern "C" void kernel_launch(void* const* d_in, const int* in_sizes, int n_in,
                              void* d_out, int out_size) {
    const float* head = (const float*)d_in[0];  // (B,S,D)
    const float* dep  = (const float*)d_in[1];  // (B,S,D)
    const float* U    = (const float*)d_in[2];  // (L,D)
    const float* W    = (const float*)d_in[3];  // (L,2D)
    const float* bias = (const float*)d_in[4];  // (L,)
    float* out = (float*)d_out;                 // (B,L,S,S)

    cudaFuncSetAttribute(biaffine_mma_kernel,
                         cudaFuncAttributeMaxDynamicSharedMemorySize, SMEM_TOTAL);

    cvt_half_kernel<<<(B_ * S_ * D_ / 4) / 256, 256>>>(head, 0);
    cvt_half_kernel<<<(B_ * S_ * D_ / 4) / 256, 256>>>(dep, 1);
    cvt_half_kernel<<<(L_ * D_ / 4) / 256, 256>>>(U, 2);
    t2_kernel<<<B_ * S_ / 8, 256>>>(head, dep, W);

    // x enumerates the 16 (i,o) tiles of one (b,l): head/dep slabs stay L2-hot.
    dim3 grid(16, 1, B_ * L_);
    biaffine_mma_kernel<<<grid, 256, SMEM_TOTAL>>>(bias, out);
}

// round 12
// speedup vs baseline: 6.5114x; 1.0316x over previous
#include <cuda_runtime.h>
#include <cuda_fp16.h>
#include <cstdint>

#define B_ 4
#define S_ 512
#define D_ 768
#define L_ 64

// ---------------------------------------------------------------------------
// Global scratch (static __device__ arrays — allocation-free at launch time)
// ---------------------------------------------------------------------------
__device__ float g_t2h[B_ * L_ * S_];
__device__ float g_t2d[B_ * L_ * S_];
__device__ __half g_head_h[B_ * S_ * D_];  // 3 MB
__device__ __half g_dep_h[B_ * S_ * D_];   // 3 MB
__device__ __half g_u_h[L_ * D_];          // 96 KB

// ---------------------------------------------------------------------------
// PTX helpers (baseline sm_80-class — legal at compute_103)
// ---------------------------------------------------------------------------
__device__ __forceinline__ uint32_t smem_to_u32(const void* p) {
    uint32_t a;
    asm("{ .reg .u64 t; cvta.to.shared.u64 t, %1; cvt.u32.u64 %0, t; }" : "=r"(a) : "l"(p));
    return a;
}
__device__ __forceinline__ void cp16(uint32_t dst, const void* src) {
    asm volatile("cp.async.cg.shared.global [%0], [%1], 16;" :: "r"(dst), "l"(src));
}
__device__ __forceinline__ void cp_commit() {
    asm volatile("cp.async.commit_group;" ::: "memory");
}
template <int N> __device__ __forceinline__ void cp_wait() {
    asm volatile("cp.async.wait_group %0;" :: "n"(N) : "memory");
}
__device__ __forceinline__ void ldsm4(uint32_t r[4], uint32_t addr) {
    asm volatile("ldmatrix.sync.aligned.m8n8.x4.shared.b16 {%0,%1,%2,%3}, [%4];"
                 : "=r"(r[0]), "=r"(r[1]), "=r"(r[2]), "=r"(r[3]) : "r"(addr));
}
__device__ __forceinline__ void mma16816(float c[4], const uint32_t a[4], const uint32_t b[2]) {
    asm volatile("mma.sync.aligned.m16n8k16.row.col.f32.f16.f16.f32 "
                 "{%0,%1,%2,%3}, {%4,%5,%6,%7}, {%8,%9}, {%0,%1,%2,%3};"
                 : "+f"(c[0]), "+f"(c[1]), "+f"(c[2]), "+f"(c[3])
                 : "r"(a[0]), "r"(a[1]), "r"(a[2]), "r"(a[3]), "r"(b[0]), "r"(b[1]));
}
__device__ __forceinline__ uint32_t ph2(float a, float b) {
    __half2 t = __floats2half2_rn(a, b);
    return *(uint32_t*)&t;
}
__device__ __forceinline__ uint32_t hm2(uint32_t a, uint32_t b) {
    __half2 x = *(__half2*)&a, y = *(__half2*)&b;
    __half2 z = __hmul2(x, y);
    return *(uint32_t*)&z;
}

// ---------------------------------------------------------------------------
// Prep 0: fp32 -> fp16 conversion (dst selected by flag; 3 launches)
// ---------------------------------------------------------------------------
__global__ void cvt_half_kernel(const float* __restrict__ src, int dst_sel) {
    __half* dst = (dst_sel == 0) ? g_head_h : (dst_sel == 1) ? g_dep_h : g_u_h;
    int idx = blockIdx.x * blockDim.x + threadIdx.x;  // one float4 per thread
    float4 v = ((const float4*)src)[idx];
    ((uint2*)dst)[idx] = make_uint2(ph2(v.x, v.y), ph2(v.z, v.w));
}

// ---------------------------------------------------------------------------
// Prep 1: rank-1 terms. Block = 8 rows x 8 labels (label groups across
// blockIdx.y for 8x the parallelism). Rows live in registers; W is L2-hot.
// grid (B*S/8, 8), block 256. Reduction order identical to the 64-label
// version -> bit-identical t2 outputs.
// ---------------------------------------------------------------------------
__global__ void t2_kernel(const float* __restrict__ head,
                          const float* __restrict__ dep,
                          const float* __restrict__ W) {
    const int b = blockIdx.x >> 6;
    const int i = (blockIdx.x & 63) * 8 + (threadIdx.x >> 5);
    const int lane = threadIdx.x & 31;
    const int l0 = blockIdx.y * 8;
    const float4* hr = (const float4*)(head + ((size_t)b * S_ + i) * D_);
    const float4* dr = (const float4*)(dep + ((size_t)b * S_ + i) * D_);
    float4 hreg[6], dreg[6];
#pragma unroll
    for (int q = 0; q < 6; q++) {
        hreg[q] = hr[lane + q * 32];
        dreg[q] = dr[lane + q * 32];
    }
#pragma unroll
    for (int lj = 0; lj < 8; lj++) {
        const int l = l0 + lj;
        const float4* Wh = (const float4*)(W + (size_t)l * (2 * D_));
        const float4* Wd = (const float4*)(W + (size_t)l * (2 * D_) + D_);
        float sh = 0.f, sd = 0.f;
#pragma unroll
        for (int q = 0; q < 6; q++) {
            float4 wh = Wh[lane + q * 32], wd = Wd[lane + q * 32];
            sh += hreg[q].x * wh.x + hreg[q].y * wh.y + hreg[q].z * wh.z + hreg[q].w * wh.w;
            sd += dreg[q].x * wd.x + dreg[q].y * wd.y + dreg[q].z * wd.z + dreg[q].w * wd.w;
        }
#pragma unroll
        for (int off = 16; off; off >>= 1) {
            sh += __shfl_down_sync(0xffffffffu, sh, off);
            sd += __shfl_down_sync(0xffffffffu, sd, off);
        }
        if (lane == 0) {
            g_t2h[((size_t)b * L_ + l) * S_ + i] = sh;
            g_t2d[((size_t)b * L_ + l) * S_ + i] = sd;
        }
    }
}

// ---------------------------------------------------------------------------
// Main GEMM: C = (head_h ⊙ U[l])·dep_h^T  (fp16 inputs, fp32 accum)
// A tiles produced IN-KERNEL: LDG head fp16 (L2-hot) -> HMUL2 with U[l]
// (fp16, staged in smem) -> STS swizzled. B via cp.async.
// 128x128 CTA tile, BK=32, 8 warps (2m x 4n, warp tile 64x32),
// 4-stage pipeline, ONE __syncthreads per k-iter, 2 CTAs/SM.
// Dynamic smem: 4 stages x (A 10240 + B 10240) + Us 1536 = 83456 B.
// ---------------------------------------------------------------------------
#define BK 32
#define NKT (D_ / BK) /* 24 */
#define LDT 40
#define TILE_B 10240
#define STAGE_B 20480
#define NSTG 4
#define OFF_US 81920
#define SMEM_TOTAL 83456

__global__ __launch_bounds__(256, 2)
void biaffine_mma_kernel(const float* __restrict__ bias,
                        float* __restrict__ out) {
    extern __shared__ __align__(16) char smem[];
    const uint32_t sb = smem_to_u32(smem);

    const int tid = threadIdx.x;
    const int wid = tid >> 5, lane = tid & 31;
    const int wm = wid & 1, wn = wid >> 1;
    const int bl = blockIdx.z;
    const int b = bl >> 6, l = bl & (L_ - 1);
    const int i0 = (blockIdx.x >> 2) * 128;
    const int o0 = (blockIdx.x & 3) * 128;

    // Stage U[l] (fp16) into smem: 768 halves = 96 uint4
    {
        const uint4* us = (const uint4*)(g_u_h + (size_t)l * D_);
        if (tid < 96) ((uint4*)(smem + OFF_US))[tid] = us[tid];
    }
    __syncthreads();

    const char* h_g = (const char*)(g_head_h + ((size_t)b * S_ + i0) * D_);
    const char* b_g = (const char*)(g_dep_h + ((size_t)b * S_ + o0) * D_);

    // Per-thread A/B staging coordinates.
    const int c0r = tid >> 2, c1r = (256 + tid) >> 2;  // c1r = c0r + 64
    const int cbi = (tid & 3) * 16;                    // byte offset (8 halves)

    uint4 apref[2];  // head chunk for the stage being produced next

#define LOAD_A_REGS(kt)                                                           \
    do {                                                                          \
        const int d0b = (kt) * (BK * 2);                                          \
        apref[0] = *(const uint4*)(h_g + (size_t)c0r * (D_ * 2) + d0b + cbi);     \
        apref[1] = *(const uint4*)(h_g + (size_t)c1r * (D_ * 2) + d0b + cbi);     \
    } while (0)

#define STORE_A(s, kt)                                                            \
    do {                                                                          \
        const int d0b = (kt) * (BK * 2);                                          \
        const uint4 uq = *(const uint4*)(smem + OFF_US + d0b + cbi);              \
        uint4 r0 = make_uint4(hm2(apref[0].x, uq.x), hm2(apref[0].y, uq.y),       \
                              hm2(apref[0].z, uq.z), hm2(apref[0].w, uq.w));      \
        uint4 r1 = make_uint4(hm2(apref[1].x, uq.x), hm2(apref[1].y, uq.y),       \
                              hm2(apref[1].z, uq.z), hm2(apref[1].w, uq.w));      \
        *(uint4*)(smem + (s) * STAGE_B + c0r * (LDT * 2) + cbi) = r0;             \
        *(uint4*)(smem + (s) * STAGE_B + c1r * (LDT * 2) + cbi) = r1;             \
    } while (0)

#define CP_B(s, kt)                                                               \
    do {                                                                          \
        const int d0b = (kt) * (BK * 2);                                          \
        cp16(sb + (s) * STAGE_B + TILE_B + c0r * (LDT * 2) + cbi,                 \
             b_g + (size_t)c0r * (D_ * 2) + d0b + cbi);                           \
        cp16(sb + (s) * STAGE_B + TILE_B + c1r * (LDT * 2) + cbi,                 \
             b_g + (size_t)c1r * (D_ * 2) + d0b + cbi);                           \
        cp_commit();                                                              \
    } while (0)

    float cacc[4][4][4];
#pragma unroll
    for (int mt = 0; mt < 4; mt++)
#pragma unroll
        for (int nt = 0; nt < 4; nt++)
#pragma unroll
            for (int q = 0; q < 4; q++) cacc[mt][nt][q] = 0.f;

    // ldmatrix lane-address byte offsets within a tile
    const uint32_t a_lm = (uint32_t)(((wm * 64 + (lane & 15)) * LDT + (lane >> 4) * 8) * 2);
    const uint32_t b_lm = (uint32_t)(((wn * 32 + (lane & 7) + ((lane >> 4) << 3)) * LDT +
                                      (((lane >> 3) & 1) * 8)) * 2);

    // ---- prologue: produce A + launch B for stages 0..2; prefetch A regs(3) ----
    LOAD_A_REGS(0);
    CP_B(0, 0);
    STORE_A(0, 0);
    LOAD_A_REGS(1);
    CP_B(1, 1);
    STORE_A(1, 1);
    LOAD_A_REGS(2);
    CP_B(2, 2);
    STORE_A(2, 2);
    LOAD_A_REGS(3);

    // ---- main loop: one sync per iteration ----
    for (int kt = 0; kt < NKT; kt++) {
        const int rem = NKT - 1 - kt;
        if (rem >= 2) cp_wait<2>();
        else if (rem == 1) cp_wait<1>();
        else cp_wait<0>();
        __syncthreads();
        // Refill stage kt+3 (consumed 3 iters from now; all warps passed its
        // last read at iter kt-1's barrier). cp.async first for earliest issue.
        if (kt + NSTG - 1 < NKT) {
            CP_B((kt + NSTG - 1) & (NSTG - 1), kt + NSTG - 1);
            STORE_A((kt + NSTG - 1) & (NSTG - 1), kt + NSTG - 1);
        }
        if (kt + NSTG < NKT) LOAD_A_REGS(kt + NSTG);

        const uint32_t stg = sb + (kt & (NSTG - 1)) * STAGE_B;
        const uint32_t baseA = stg + a_lm;
        const uint32_t baseB = stg + TILE_B + b_lm;
#pragma unroll
        for (int ks = 0; ks < 2; ks++) {
            const uint32_t ko = ks * 32;  // 16 fp16 * 2 B
            uint32_t bh[4][2];
#pragma unroll
            for (int nt2 = 0; nt2 < 2; nt2++) {
                uint32_t t[4];
                ldsm4(t, baseB + nt2 * (16 * LDT * 2) + ko);
                bh[nt2 * 2][0] = t[0]; bh[nt2 * 2][1] = t[1];
                bh[nt2 * 2 + 1][0] = t[2]; bh[nt2 * 2 + 1][1] = t[3];
            }
#pragma unroll
            for (int mt = 0; mt < 4; mt++) {
                uint32_t ah[4];
                ldsm4(ah, baseA + mt * (16 * LDT * 2) + ko);
#pragma unroll
                for (int nt = 0; nt < 4; nt++) mma16816(cacc[mt][nt], ah, bh[nt]);
            }
        }
    }

    // ---- epilogue: + t2h[i] + t2d[o] + bias[l] ----
    const float* t2h = g_t2h + (size_t)bl * S_;
    const float* t2d = g_t2d + (size_t)bl * S_;
    const float bz = bias[l];
    float* obase = out + (size_t)bl * S_ * S_;
#pragma unroll
    for (int mt = 0; mt < 4; mt++) {
        const int i_lo = i0 + wm * 64 + mt * 16 + (lane >> 2);
        const float ai0 = t2h[i_lo] + bz;
        const float ai1 = t2h[i_lo + 8] + bz;
        float* row0 = obase + (size_t)i_lo * S_;
        float* row1 = row0 + 8 * S_;
#pragma unroll
        for (int nt = 0; nt < 4; nt++) {
            const int o_ = o0 + wn * 32 + nt * 8 + (lane & 3) * 2;
            const float td0 = t2d[o_], td1 = t2d[o_ + 1];
            *(float2*)(row0 + o_) =
                make_float2(cacc[mt][nt][0] + td0 + ai0, cacc[mt][nt][1] + td1 + ai0);
            *(float2*)(row1 + o_) =
                make_float2(cacc[mt][nt][2] + td0 + ai1, cacc[mt][nt][3] + td1 + ai1);
        }
    }
#undef LOAD_A_REGS
#undef STORE_A
#undef CP_B
}

// ---------------------------------------------------------------------------
extern "C" void kernel_launch(void* const* d_in, const int* in_sizes, int n_in,
                              void* d_out, int out_size) {
    const float* head = (const float*)d_in[0];  // (B,S,D)
    const float* dep  = (const float*)d_in[1];  // (B,S,D)
    const float* U    = (const float*)d_in[2];  // (L,D)
    const float* W    = (const float*)d_in[3];  // (L,2D)
    const float* bias = (const float*)d_in[4];  // (L,)
    float* out = (float*)d_out;                 // (B,L,S,S)

    cudaFuncSetAttribute(biaffine_mma_kernel,
                         cudaFuncAttributeMaxDynamicSharedMemorySize, SMEM_TOTAL);

    cvt_half_kernel<<<(B_ * S_ * D_ / 4) / 256, 256>>>(head, 0);
    cvt_half_kernel<<<(B_ * S_ * D_ / 4) / 256, 256>>>(dep, 1);
    cvt_half_kernel<<<(L_ * D_ / 4) / 256, 256>>>(U, 2);
    t2_kernel<<<dim3(B_ * S_ / 8, 8), 256>>>(head, dep, W);

    // x enumerates the 16 (i,o) tiles of one (b,l): head/dep slabs stay L2-hot.
    dim3 grid(16, 1, B_ * L_);
    biaffine_mma_kernel<<<grid, 256, SMEM_TOTAL>>>(bias, out);
}